// round 1
// baseline (speedup 1.0000x reference)
#include <cuda_runtime.h>

#define D        256
#define HEADS    8
#define DH       2048     // D*HEADS
#define TM       32       // tokens per CTA
#define NTHREADS 256

#define SQ_PITCH 36       // 144B rows -> 16B aligned for LDS.128 broadcast reads
#define SK_PITCH 33       // odd pitch -> conflict-free strided reads/writes

// shared memory layout (floats)
#define OFF_X   0
#define OFF_Q   (OFF_X + D * TM)                  // 8192
#define OFF_K   (OFF_Q + 256 * SQ_PITCH)          // + 9216
#define OFF_P   (OFF_K + 256 * SK_PITCH)          // + 8448
#define SMEM_FLOATS (OFF_P + TM * HEADS * HEADS)  // + 2048 = 27904 floats = 111616 B

// ---- packed f32x2 helpers (B300: FFMA2 gives 2x fp32 FMA rate vs 3-reg FFMA) ----
__device__ __forceinline__ unsigned long long pack2(float x, float y) {
    unsigned long long r;
    asm("mov.b64 %0, {%1, %2};" : "=l"(r) : "f"(x), "f"(y));
    return r;
}
__device__ __forceinline__ void unpack2(unsigned long long v, float& x, float& y) {
    asm("mov.b64 {%0, %1}, %2;" : "=f"(x), "=f"(y) : "l"(v));
}
__device__ __forceinline__ unsigned long long fma2(unsigned long long a,
                                                   unsigned long long b,
                                                   unsigned long long c) {
    unsigned long long d;
    asm("fma.rn.f32x2 %0, %1, %2, %3;" : "=l"(d) : "l"(a), "l"(b), "l"(c));
    return d;
}

__global__ void __launch_bounds__(NTHREADS, 2)
attn_fused_kernel(const float* __restrict__ x,
                  const float* __restrict__ Wq, const float* __restrict__ bq,
                  const float* __restrict__ Wk, const float* __restrict__ bk,
                  const float* __restrict__ Wv, const float* __restrict__ bv,
                  const float* __restrict__ Wo, const float* __restrict__ bo,
                  float* __restrict__ out)
{
    extern __shared__ float sm[];
    float* sX = sm + OFF_X;   // [k][t]   k*32 + t
    float* sQ = sm + OFF_Q;   // [c][t]   c*36 + t   (reused as sO in phase 3)
    float* sK = sm + OFF_K;   // [c][t]   c*33 + t   (reused as sV in phase 3)
    float* sP = sm + OFF_P;   // [t][h][g]

    const int tid = threadIdx.x;
    const int g0  = blockIdx.x * TM;   // first token of this tile

    // ---------------- phase 0: load X tile ----------------
    {
        const float* xin = x + g0 * D;
        for (int i = tid; i < TM * D; i += NTHREADS) {
            int t = i >> 8;          // i / 256
            int k = i & (D - 1);
            sX[k * TM + t] = xin[i];
        }
    }
    __syncthreads();

    const int head = tid >> 5;   // 0..7   (column-group mapping for GEMMs)
    const int dd   = tid & 31;
    const int lt   = tid >> 3;   // 0..31  (token mapping for logits/softmax)
    const int lh   = tid & 7;    // 0..7

    float accL[HEADS];
    #pragma unroll
    for (int g = 0; g < HEADS; g++) accL[g] = 0.f;

    // ---------------- phase 1: Q/K projection chunks + logit accumulation ----------------
    for (int dc = 0; dc < 8; dc++) {
        const int j = head * D + dc * 32 + dd;   // weight column for this thread
        unsigned long long aq[16], ak[16];
        #pragma unroll
        for (int i = 0; i < 16; i++) { aq[i] = 0ull; ak[i] = 0ull; }
        const float* wqp = Wq + j;
        const float* wkp = Wk + j;
        #pragma unroll 4
        for (int k = 0; k < D; k++) {
            float wqv = wqp[k * DH];
            float wkv = wkp[k * DH];
            unsigned long long wq2 = pack2(wqv, wqv);
            unsigned long long wk2 = pack2(wkv, wkv);
            const ulonglong2* xv = reinterpret_cast<const ulonglong2*>(sX + k * TM);
            #pragma unroll
            for (int tt = 0; tt < 8; tt++) {
                ulonglong2 xp = xv[tt];          // 4 tokens, broadcast LDS.128
                aq[2*tt]   = fma2(xp.x, wq2, aq[2*tt]);
                aq[2*tt+1] = fma2(xp.y, wq2, aq[2*tt+1]);
                ak[2*tt]   = fma2(xp.x, wk2, ak[2*tt]);
                ak[2*tt+1] = fma2(xp.y, wk2, ak[2*tt+1]);
            }
        }
        const float bqv = bq[j];
        const float bkv = bk[j];
        #pragma unroll
        for (int i = 0; i < 16; i++) {
            float f0, f1;
            unpack2(aq[i], f0, f1);
            sQ[tid * SQ_PITCH + 2*i]     = f0 + bqv;
            sQ[tid * SQ_PITCH + 2*i + 1] = f1 + bqv;
            unpack2(ak[i], f0, f1);
            sK[tid * SK_PITCH + 2*i]     = f0 + bkv;
            sK[tid * SK_PITCH + 2*i + 1] = f1 + bkv;
        }
        __syncthreads();
        // logit accumulation: thread owns token lt, query-head lh
        #pragma unroll 4
        for (int d2 = 0; d2 < 32; d2++) {
            float qv = sQ[(lh * 32 + d2) * SQ_PITCH + lt];
            #pragma unroll
            for (int g = 0; g < HEADS; g++)
                accL[g] = fmaf(qv, sK[(g * 32 + d2) * SK_PITCH + lt], accL[g]);
        }
        __syncthreads();
    }

    // ---------------- phase 2: softmax (8-wide, per (token, head) in registers) ----------------
    {
        const float scale = 0.0625f;   // 256^-0.5
        float m = -3.4e38f;
        #pragma unroll
        for (int g = 0; g < HEADS; g++) { accL[g] *= scale; m = fmaxf(m, accL[g]); }
        float s = 0.f;
        #pragma unroll
        for (int g = 0; g < HEADS; g++) { accL[g] = expf(accL[g] - m); s += accL[g]; }
        const float inv = 1.f / s;
        #pragma unroll
        for (int g = 0; g < HEADS; g++)
            sP[(lt * HEADS + lh) * HEADS + g] = accL[g] * inv;
    }
    // visibility of sP is guaranteed by the __syncthreads() inside phase 3 before first read

    // ---------------- phase 3: V chunks -> O chunks -> streamed output GEMM ----------------
    unsigned long long ay[16];
    #pragma unroll
    for (int i = 0; i < 16; i++) ay[i] = 0ull;

    for (int dc = 0; dc < 8; dc++) {
        // (a) V chunk: V[t, g*32+dd] for d-range dc
        const int j = head * D + dc * 32 + dd;
        unsigned long long av[16];
        #pragma unroll
        for (int i = 0; i < 16; i++) av[i] = 0ull;
        const float* wvp = Wv + j;
        #pragma unroll 4
        for (int k = 0; k < D; k++) {
            float wvv = wvp[k * DH];
            unsigned long long wv2 = pack2(wvv, wvv);
            const ulonglong2* xv = reinterpret_cast<const ulonglong2*>(sX + k * TM);
            #pragma unroll
            for (int tt = 0; tt < 8; tt++) {
                ulonglong2 xp = xv[tt];
                av[2*tt]   = fma2(xp.x, wv2, av[2*tt]);
                av[2*tt+1] = fma2(xp.y, wv2, av[2*tt+1]);
            }
        }
        const float bvv = bv[j];
        #pragma unroll
        for (int i = 0; i < 16; i++) {
            float f0, f1;
            unpack2(av[i], f0, f1);
            sK[tid * SK_PITCH + 2*i]     = f0 + bvv;   // sV lives in sK buffer
            sK[tid * SK_PITCH + 2*i + 1] = f1 + bvv;
        }
        __syncthreads();

        // (b) O chunk: O[t, head*32+dd] = sum_g P[t,head,g] * V[t, g*32+dd]
        #pragma unroll 4
        for (int t = 0; t < TM; t++) {
            const float* pp = sP + (t * HEADS + head) * HEADS;   // broadcast across warp
            float o = 0.f;
            #pragma unroll
            for (int g = 0; g < HEADS; g++)
                o = fmaf(pp[g], sK[(g * 32 + dd) * SK_PITCH + t], o);
            sQ[tid * SQ_PITCH + t] = o;    // sO lives in sQ buffer
        }
        __syncthreads();

        // (c) Y accumulation: thread owns output column n = tid
        const int wbase = dc * 32;
        #pragma unroll 4
        for (int c2 = 0; c2 < 256; c2++) {
            const int wr = (c2 >> 5) * D + wbase + (c2 & 31);    // Wo row for O-chunk col c2
            float wo = Wo[wr * D + tid];
            unsigned long long wo2 = pack2(wo, wo);
            const ulonglong2* ov = reinterpret_cast<const ulonglong2*>(sQ + c2 * SQ_PITCH);
            #pragma unroll
            for (int tt = 0; tt < 8; tt++) {
                ulonglong2 op = ov[tt];
                ay[2*tt]   = fma2(op.x, wo2, ay[2*tt]);
                ay[2*tt+1] = fma2(op.y, wo2, ay[2*tt+1]);
            }
        }
        __syncthreads();
    }

    // ---------------- phase 4: bias + coalesced writeout ----------------
    const float bov = bo[tid];
    float yv[TM];
    #pragma unroll
    for (int i = 0; i < 16; i++) unpack2(ay[i], yv[2*i], yv[2*i+1]);
    float* op = out + g0 * D + tid;
    #pragma unroll
    for (int t = 0; t < TM; t++)
        op[t * D] = yv[t] + bov;
}

extern "C" void kernel_launch(void* const* d_in, const int* in_sizes, int n_in,
                              void* d_out, int out_size) {
    const float* x  = (const float*)d_in[0];
    const float* Wq = (const float*)d_in[1];
    const float* bq = (const float*)d_in[2];
    const float* Wk = (const float*)d_in[3];
    const float* bk = (const float*)d_in[4];
    const float* Wv = (const float*)d_in[5];
    const float* bv = (const float*)d_in[6];
    const float* Wo = (const float*)d_in[7];
    const float* bo = (const float*)d_in[8];
    float* out = (float*)d_out;

    const int T = in_sizes[0] / D;          // 16384 tokens
    const int grid = T / TM;                // 512 CTAs
    const size_t smem = SMEM_FLOATS * sizeof(float);

    cudaFuncSetAttribute(attn_fused_kernel,
                         cudaFuncAttributeMaxDynamicSharedMemorySize, (int)smem);
    attn_fused_kernel<<<grid, NTHREADS, smem>>>(x, Wq, bq, Wk, bk, Wv, bv, Wo, bo, out);
}

// round 2
// speedup vs baseline: 1.0004x; 1.0004x over previous
#include <cuda_runtime.h>

#define D        256
#define HEADS    8
#define DH       2048     // D*HEADS
#define TM       32       // tokens per CTA
#define NTHREADS 256

#define SQ_PITCH 36       // 144B rows -> 16B aligned for LDS.128 broadcast reads
#define SK_PITCH 33       // odd pitch -> conflict-free strided reads/writes

// shared memory layout (floats)
#define OFF_X   0
#define OFF_Q   (OFF_X + D * TM)                  // 8192
#define OFF_K   (OFF_Q + 256 * SQ_PITCH)          // + 9216
#define OFF_P   (OFF_K + 256 * SK_PITCH)          // + 8448
#define SMEM_FLOATS (OFF_P + TM * HEADS * HEADS)  // + 2048 = 27904 floats = 111616 B

// ---- packed f32x2 helpers (B300: FFMA2 gives 2x fp32 FMA rate vs 3-reg FFMA) ----
__device__ __forceinline__ unsigned long long pack2(float x, float y) {
    unsigned long long r;
    asm("mov.b64 %0, {%1, %2};" : "=l"(r) : "f"(x), "f"(y));
    return r;
}
__device__ __forceinline__ void unpack2(unsigned long long v, float& x, float& y) {
    asm("mov.b64 {%0, %1}, %2;" : "=f"(x), "=f"(y) : "l"(v));
}
__device__ __forceinline__ unsigned long long fma2(unsigned long long a,
                                                   unsigned long long b,
                                                   unsigned long long c) {
    unsigned long long d;
    asm("fma.rn.f32x2 %0, %1, %2, %3;" : "=l"(d) : "l"(a), "l"(b), "l"(c));
    return d;
}

__global__ void __launch_bounds__(NTHREADS, 2)
attn_fused_kernel(const float* __restrict__ x,
                  const float* __restrict__ Wq, const float* __restrict__ bq,
                  const float* __restrict__ Wk, const float* __restrict__ bk,
                  const float* __restrict__ Wv, const float* __restrict__ bv,
                  const float* __restrict__ Wo, const float* __restrict__ bo,
                  float* __restrict__ out)
{
    extern __shared__ float sm[];
    float* sX = sm + OFF_X;   // [k][t]   k*32 + t
    float* sQ = sm + OFF_Q;   // [c][t]   c*36 + t   (reused as sO in phase 3)
    float* sK = sm + OFF_K;   // [c][t]   c*33 + t   (reused as sV in phase 3)
    float* sP = sm + OFF_P;   // [t][h][g]

    const int tid = threadIdx.x;
    const int g0  = blockIdx.x * TM;   // first token of this tile

    // ---------------- phase 0: load X tile ----------------
    {
        const float* xin = x + g0 * D;
        for (int i = tid; i < TM * D; i += NTHREADS) {
            int t = i >> 8;          // i / 256
            int k = i & (D - 1);
            sX[k * TM + t] = xin[i];
        }
    }
    __syncthreads();

    const int head = tid >> 5;   // 0..7   (column-group mapping for GEMMs)
    const int dd   = tid & 31;
    const int lt   = tid >> 3;   // 0..31  (token mapping for logits/softmax)
    const int lh   = tid & 7;    // 0..7

    float accL[HEADS];
    #pragma unroll
    for (int g = 0; g < HEADS; g++) accL[g] = 0.f;

    // ---------------- phase 1: Q/K projection chunks + logit accumulation ----------------
    for (int dc = 0; dc < 8; dc++) {
        const int j = head * D + dc * 32 + dd;   // weight column for this thread
        unsigned long long aq[16], ak[16];
        #pragma unroll
        for (int i = 0; i < 16; i++) { aq[i] = 0ull; ak[i] = 0ull; }
        const float* wqp = Wq + j;
        const float* wkp = Wk + j;
        #pragma unroll 4
        for (int k = 0; k < D; k++) {
            float wqv = wqp[k * DH];
            float wkv = wkp[k * DH];
            unsigned long long wq2 = pack2(wqv, wqv);
            unsigned long long wk2 = pack2(wkv, wkv);
            const ulonglong2* xv = reinterpret_cast<const ulonglong2*>(sX + k * TM);
            #pragma unroll
            for (int tt = 0; tt < 8; tt++) {
                ulonglong2 xp = xv[tt];          // 4 tokens, broadcast LDS.128
                aq[2*tt]   = fma2(xp.x, wq2, aq[2*tt]);
                aq[2*tt+1] = fma2(xp.y, wq2, aq[2*tt+1]);
                ak[2*tt]   = fma2(xp.x, wk2, ak[2*tt]);
                ak[2*tt+1] = fma2(xp.y, wk2, ak[2*tt+1]);
            }
        }
        const float bqv = bq[j];
        const float bkv = bk[j];
        #pragma unroll
        for (int i = 0; i < 16; i++) {
            float f0, f1;
            unpack2(aq[i], f0, f1);
            sQ[tid * SQ_PITCH + 2*i]     = f0 + bqv;
            sQ[tid * SQ_PITCH + 2*i + 1] = f1 + bqv;
            unpack2(ak[i], f0, f1);
            sK[tid * SK_PITCH + 2*i]     = f0 + bkv;
            sK[tid * SK_PITCH + 2*i + 1] = f1 + bkv;
        }
        __syncthreads();
        // logit accumulation: thread owns token lt, query-head lh
        #pragma unroll 4
        for (int d2 = 0; d2 < 32; d2++) {
            float qv = sQ[(lh * 32 + d2) * SQ_PITCH + lt];
            #pragma unroll
            for (int g = 0; g < HEADS; g++)
                accL[g] = fmaf(qv, sK[(g * 32 + d2) * SK_PITCH + lt], accL[g]);
        }
        __syncthreads();
    }

    // ---------------- phase 2: softmax (8-wide, per (token, head) in registers) ----------------
    {
        const float scale = 0.0625f;   // 256^-0.5
        float m = -3.4e38f;
        #pragma unroll
        for (int g = 0; g < HEADS; g++) { accL[g] *= scale; m = fmaxf(m, accL[g]); }
        float s = 0.f;
        #pragma unroll
        for (int g = 0; g < HEADS; g++) { accL[g] = expf(accL[g] - m); s += accL[g]; }
        const float inv = 1.f / s;
        #pragma unroll
        for (int g = 0; g < HEADS; g++)
            sP[(lt * HEADS + lh) * HEADS + g] = accL[g] * inv;
    }
    // visibility of sP is guaranteed by the __syncthreads() inside phase 3 before first read

    // ---------------- phase 3: V chunks -> O chunks -> streamed output GEMM ----------------
    unsigned long long ay[16];
    #pragma unroll
    for (int i = 0; i < 16; i++) ay[i] = 0ull;

    for (int dc = 0; dc < 8; dc++) {
        // (a) V chunk: V[t, g*32+dd] for d-range dc
        const int j = head * D + dc * 32 + dd;
        unsigned long long av[16];
        #pragma unroll
        for (int i = 0; i < 16; i++) av[i] = 0ull;
        const float* wvp = Wv + j;
        #pragma unroll 4
        for (int k = 0; k < D; k++) {
            float wvv = wvp[k * DH];
            unsigned long long wv2 = pack2(wvv, wvv);
            const ulonglong2* xv = reinterpret_cast<const ulonglong2*>(sX + k * TM);
            #pragma unroll
            for (int tt = 0; tt < 8; tt++) {
                ulonglong2 xp = xv[tt];
                av[2*tt]   = fma2(xp.x, wv2, av[2*tt]);
                av[2*tt+1] = fma2(xp.y, wv2, av[2*tt+1]);
            }
        }
        const float bvv = bv[j];
        #pragma unroll
        for (int i = 0; i < 16; i++) {
            float f0, f1;
            unpack2(av[i], f0, f1);
            sK[tid * SK_PITCH + 2*i]     = f0 + bvv;   // sV lives in sK buffer
            sK[tid * SK_PITCH + 2*i + 1] = f1 + bvv;
        }
        __syncthreads();

        // (b) O chunk: O[t, head*32+dd] = sum_g P[t,head,g] * V[t, g*32+dd]
        #pragma unroll 4
        for (int t = 0; t < TM; t++) {
            const float* pp = sP + (t * HEADS + head) * HEADS;   // broadcast across warp
            float o = 0.f;
            #pragma unroll
            for (int g = 0; g < HEADS; g++)
                o = fmaf(pp[g], sK[(g * 32 + dd) * SK_PITCH + t], o);
            sQ[tid * SQ_PITCH + t] = o;    // sO lives in sQ buffer
        }
        __syncthreads();

        // (c) Y accumulation: thread owns output column n = tid
        const int wbase = dc * 32;
        #pragma unroll 4
        for (int c2 = 0; c2 < 256; c2++) {
            const int wr = (c2 >> 5) * D + wbase + (c2 & 31);    // Wo row for O-chunk col c2
            float wo = Wo[wr * D + tid];
            unsigned long long wo2 = pack2(wo, wo);
            const ulonglong2* ov = reinterpret_cast<const ulonglong2*>(sQ + c2 * SQ_PITCH);
            #pragma unroll
            for (int tt = 0; tt < 8; tt++) {
                ulonglong2 op = ov[tt];
                ay[2*tt]   = fma2(op.x, wo2, ay[2*tt]);
                ay[2*tt+1] = fma2(op.y, wo2, ay[2*tt+1]);
            }
        }
        __syncthreads();
    }

    // ---------------- phase 4: bias + coalesced writeout ----------------
    const float bov = bo[tid];
    float yv[TM];
    #pragma unroll
    for (int i = 0; i < 16; i++) unpack2(ay[i], yv[2*i], yv[2*i+1]);
    float* op = out + g0 * D + tid;
    #pragma unroll
    for (int t = 0; t < TM; t++)
        op[t * D] = yv[t] + bov;
}

extern "C" void kernel_launch(void* const* d_in, const int* in_sizes, int n_in,
                              void* d_out, int out_size) {
    const float* x  = (const float*)d_in[0];
    const float* Wq = (const float*)d_in[1];
    const float* bq = (const float*)d_in[2];
    const float* Wk = (const float*)d_in[3];
    const float* bk = (const float*)d_in[4];
    const float* Wv = (const float*)d_in[5];
    const float* bv = (const float*)d_in[6];
    const float* Wo = (const float*)d_in[7];
    const float* bo = (const float*)d_in[8];
    float* out = (float*)d_out;

    const int T = in_sizes[0] / D;          // 16384 tokens
    const int grid = T / TM;                // 512 CTAs
    const size_t smem = SMEM_FLOATS * sizeof(float);

    cudaFuncSetAttribute(attn_fused_kernel,
                         cudaFuncAttributeMaxDynamicSharedMemorySize, (int)smem);
    attn_fused_kernel<<<grid, NTHREADS, smem>>>(x, Wq, bq, Wk, bk, Wv, bv, Wo, bo, out);
}